// round 5
// baseline (speedup 1.0000x reference)
#include <cuda_runtime.h>
#include <cuda_bf16.h>

// ---------------------------------------------------------------------------
// RandomSpatialDeformation: svf upsample -> scaling&squaring (7) -> upsample
// -> affine+flow warp of x.
// Flow fields stored as float4 (z,y,x,0) so every trilinear tap is 1x LDG.128.
// k_square / k_final process 2 adjacent-x outputs per thread for load-level
// parallelism (R4 showed them latency-bound, not op-bound).
// ---------------------------------------------------------------------------

#define BATCH 2
#define SV    10
#define CDIM  80
#define FDIM  160

#define C2 (CDIM * CDIM)
#define C3 (CDIM * CDIM * CDIM)          // 512000
#define F2 (FDIM * FDIM)
#define F3 (FDIM * FDIM * FDIM)          // 4096000

#define BC3 (BATCH * C3)                 // 1024000
#define BF3 (BATCH * F3)                 // 8192000

#define CX2 (CDIM / 2)                   // 40
#define FX2 (FDIM / 2)                   // 80

__device__ float4 g_v4a[BC3];            // 16.4 MB
__device__ float4 g_v4b[BC3];            // 16.4 MB
__device__ float4 g_u4[BF3];             // 131 MB

__device__ __forceinline__ float flerp(float a, float b, float t) {
    return fmaf(t, b - a, a);
}
__device__ __forceinline__ float4 flerp4(float4 a, float4 b, float t) {
    return make_float4(fmaf(t, b.x - a.x, a.x), fmaf(t, b.y - a.y, a.y),
                       fmaf(t, b.z - a.z, a.z), fmaf(t, b.w - a.w, a.w));
}
__device__ __forceinline__ float4 fmadd4(float4 acc, float4 v, float w) {
    return make_float4(fmaf(w, v.x, acc.x), fmaf(w, v.y, acc.y),
                       fmaf(w, v.z, acc.z), fmaf(w, v.w, acc.w));
}
__device__ __forceinline__ float4 fscale4(float4 v, float w) {
    return make_float4(v.x * w, v.y * w, v.z * w, v.w * w);
}

// Trilinear sample of a float4 volume, D^3 spatial, clamped.
template <int D>
__device__ __forceinline__ float4 trisample4(const float4* __restrict__ vol,
                                             float z, float y, float x) {
    const float mx = (float)(D - 1);
    z = fminf(fmaxf(z, 0.0f), mx);
    y = fminf(fmaxf(y, 0.0f), mx);
    x = fminf(fmaxf(x, 0.0f), mx);
    float fz = floorf(z), fy = floorf(y), fx = floorf(x);
    int iz = (int)fz, iy = (int)fy, ix = (int)fx;
    float wz = z - fz, wy = y - fy, wx = x - fx;
    int iz1 = min(iz + 1, D - 1);
    int iy1 = min(iy + 1, D - 1);
    int ix1 = min(ix + 1, D - 1);

    const float4* p00 = vol + iz * (D * D) + iy * D;
    const float4* p01 = vol + iz * (D * D) + iy1 * D;
    const float4* p10 = vol + iz1 * (D * D) + iy * D;
    const float4* p11 = vol + iz1 * (D * D) + iy1 * D;

    float4 a0 = flerp4(p00[ix], p00[ix1], wx);
    float4 a1 = flerp4(p01[ix], p01[ix1], wx);
    float4 a2 = flerp4(p10[ix], p10[ix1], wx);
    float4 a3 = flerp4(p11[ix], p11[ix1], wx);
    return flerp4(flerp4(a0, a1, wy), flerp4(a2, a3, wy), wz);
}

// Scalar trilinear sample (for the image x), D^3 spatial, clamped.
template <int D>
__device__ __forceinline__ float trisample1(const float* __restrict__ vol,
                                            float z, float y, float x) {
    const float mx = (float)(D - 1);
    z = fminf(fmaxf(z, 0.0f), mx);
    y = fminf(fmaxf(y, 0.0f), mx);
    x = fminf(fmaxf(x, 0.0f), mx);
    float fz = floorf(z), fy = floorf(y), fx = floorf(x);
    int iz = (int)fz, iy = (int)fy, ix = (int)fx;
    float wz = z - fz, wy = y - fy, wx = x - fx;
    int iz1 = min(iz + 1, D - 1);
    int iy1 = min(iy + 1, D - 1);
    int ix1 = min(ix + 1, D - 1);

    const float* p00 = vol + iz * (D * D) + iy * D;
    const float* p01 = vol + iz * (D * D) + iy1 * D;
    const float* p10 = vol + iz1 * (D * D) + iy * D;
    const float* p11 = vol + iz1 * (D * D) + iy1 * D;

    float a0 = flerp(p00[ix], p00[ix1], wx);
    float a1 = flerp(p01[ix], p01[ix1], wx);
    float a2 = flerp(p10[ix], p10[ix1], wx);
    float a3 = flerp(p11[ix], p11[ix1], wx);
    return flerp(flerp(a0, a1, wy), flerp(a2, a3, wy), wz);
}

// K1: resize svf [B,10,10,10,3] (AoS) -> g_v4a [B,80^3] float4, * 2^-7.
__global__ void __launch_bounds__(256) k_resize_svf(const float* __restrict__ svf) {
    int idx = blockIdx.x * 256 + threadIdx.x;
    if (idx >= BC3) return;
    int x = idx % CDIM;
    int y = (idx / CDIM) % CDIM;
    int z = (idx / C2) % CDIM;
    int b = idx / C3;

    float cz = (float)z * 0.125f - 0.4375f;
    float cy = (float)y * 0.125f - 0.4375f;
    float cx = (float)x * 0.125f - 0.4375f;
    const float mx = (float)(SV - 1);
    cz = fminf(fmaxf(cz, 0.0f), mx);
    cy = fminf(fmaxf(cy, 0.0f), mx);
    cx = fminf(fmaxf(cx, 0.0f), mx);
    float fz = floorf(cz), fy = floorf(cy), fx = floorf(cx);
    int iz = (int)fz, iy = (int)fy, ix = (int)fx;
    float wz = cz - fz, wy = cy - fy, wx = cx - fx;
    int iz1 = min(iz + 1, SV - 1);
    int iy1 = min(iy + 1, SV - 1);
    int ix1 = min(ix + 1, SV - 1);

    int base = b * SV * SV * SV;
    int p000 = (base + iz * SV * SV + iy * SV + ix) * 3;
    int p001 = (base + iz * SV * SV + iy * SV + ix1) * 3;
    int p010 = (base + iz * SV * SV + iy1 * SV + ix) * 3;
    int p011 = (base + iz * SV * SV + iy1 * SV + ix1) * 3;
    int p100 = (base + iz1 * SV * SV + iy * SV + ix) * 3;
    int p101 = (base + iz1 * SV * SV + iy * SV + ix1) * 3;
    int p110 = (base + iz1 * SV * SV + iy1 * SV + ix) * 3;
    int p111 = (base + iz1 * SV * SV + iy1 * SV + ix1) * 3;

    float r[3];
#pragma unroll
    for (int c = 0; c < 3; c++) {
        float a0 = flerp(svf[p000 + c], svf[p001 + c], wx);
        float a1 = flerp(svf[p010 + c], svf[p011 + c], wx);
        float a2 = flerp(svf[p100 + c], svf[p101 + c], wx);
        float a3 = flerp(svf[p110 + c], svf[p111 + c], wx);
        float b0 = flerp(a0, a1, wy);
        float b1 = flerp(a2, a3, wy);
        r[c] = flerp(b0, b1, wz) * (1.0f / 128.0f);
    }
    g_v4a[b * C3 + z * C2 + y * CDIM + x] = make_float4(r[0], r[1], r[2], 0.0f);
}

// K2: squaring step dst = v + trilinear(v, p + v). DIR=0: a->b, 1: b->a.
// 2 adjacent-x outputs per thread (independent chains -> 2x MLP).
template <int DIR>
__global__ void __launch_bounds__(256) k_square() {
    const float4* __restrict__ src = DIR ? g_v4b : g_v4a;
    float4* __restrict__ dst = DIR ? g_v4a : g_v4b;
    int idx = blockIdx.x * 256 + threadIdx.x;
    if (idx >= BC3 / 2) return;
    int x2 = idx % CX2;
    int t = idx / CX2;
    int y = t % CDIM;
    t /= CDIM;
    int z = t % CDIM;
    int b = t / CDIM;
    int x0 = 2 * x2;

    int lin = b * C3 + z * C2 + y * CDIM + x0;
    float4 v0 = src[lin];
    float4 v1 = src[lin + 1];

    const float4* vb = src + b * C3;
    float4 s0 = trisample4<CDIM>(vb, (float)z + v0.x, (float)y + v0.y, (float)x0 + v0.z);
    float4 s1 = trisample4<CDIM>(vb, (float)z + v1.x, (float)y + v1.y, (float)(x0 + 1) + v1.z);

    dst[lin]     = make_float4(v0.x + s0.x, v0.y + s0.y, v0.z + s0.z, 0.0f);
    dst[lin + 1] = make_float4(v1.x + s1.x, v1.y + s1.y, v1.z + s1.z, 0.0f);
}

// K3: 80^3 -> 160^3 upsample, blocked: each thread emits a 2x2x2 fine block
// from a 3x3x3 coarse neighborhood. Fixed weights by parity: even fine k'=2k:
// 0.25*c[k-1] + 0.75*c[k]; odd k'=2k+1: 0.75*c[k] + 0.25*c[k+1] (clamped).
__global__ void __launch_bounds__(256) k_upsample() {
    int idx = blockIdx.x * 256 + threadIdx.x;
    if (idx >= BC3) return;
    int xb = idx % CDIM;
    int yb = (idx / CDIM) % CDIM;
    int zb = (idx / C2) % CDIM;
    int b = idx / C3;

    int im1 = max(xb - 1, 0), ip1 = min(xb + 1, CDIM - 1);
    int jm1 = max(yb - 1, 0), jp1 = min(yb + 1, CDIM - 1);
    int km1 = max(zb - 1, 0), kp1 = min(zb + 1, CDIM - 1);

    const float4* __restrict__ v = g_v4b + b * C3;
    int zoff[3] = { km1 * C2, zb * C2, kp1 * C2 };
    int yoff[3] = { jm1 * CDIM, yb * CDIM, jp1 * CDIM };

    float4 acc[2][2][2];
#pragma unroll
    for (int a = 0; a < 2; a++)
#pragma unroll
        for (int bb = 0; bb < 2; bb++)
#pragma unroll
            for (int c = 0; c < 2; c++)
                acc[a][bb][c] = make_float4(0.f, 0.f, 0.f, 0.f);

    const float wze[3] = { 0.25f, 0.75f, 0.0f };
    const float wzo[3] = { 0.0f,  0.75f, 0.25f };

#pragma unroll
    for (int p = 0; p < 3; p++) {
        float we = wze[p], wo = wzo[p];
        float4 xe[3], xo[3];
#pragma unroll
        for (int r = 0; r < 3; r++) {
            const float4* row = v + zoff[p] + yoff[r];
            float4 cm1 = row[im1];
            float4 c0  = row[xb];
            float4 cp1 = row[ip1];
            xe[r] = fmadd4(fscale4(cm1, 0.25f), c0, 0.75f);
            xo[r] = fmadd4(fscale4(cp1, 0.25f), c0, 0.75f);
        }
        float4 pv[2][2];
        pv[0][0] = fmadd4(fscale4(xe[0], 0.25f), xe[1], 0.75f);
        pv[0][1] = fmadd4(fscale4(xo[0], 0.25f), xo[1], 0.75f);
        pv[1][0] = fmadd4(fscale4(xe[2], 0.25f), xe[1], 0.75f);
        pv[1][1] = fmadd4(fscale4(xo[2], 0.25f), xo[1], 0.75f);
#pragma unroll
        for (int dy = 0; dy < 2; dy++)
#pragma unroll
            for (int dx = 0; dx < 2; dx++) {
                if (we != 0.0f) acc[0][dy][dx] = fmadd4(acc[0][dy][dx], pv[dy][dx], we);
                if (wo != 0.0f) acc[1][dy][dx] = fmadd4(acc[1][dy][dx], pv[dy][dx], wo);
            }
    }

    float4* __restrict__ u = g_u4 + b * F3;
    int fz = 2 * zb, fy = 2 * yb, fx = 2 * xb;
#pragma unroll
    for (int dz = 0; dz < 2; dz++)
#pragma unroll
        for (int dy = 0; dy < 2; dy++)
#pragma unroll
            for (int dx = 0; dx < 2; dx++)
                u[(fz + dz) * F2 + (fy + dy) * FDIM + (fx + dx)] = acc[dz][dy][dx];
}

// K4: fused affine + flow sample + image sample. 2 adjacent-x outputs/thread.
__global__ void __launch_bounds__(256) k_final(const float* __restrict__ xin,
                                               const float* __restrict__ aff,
                                               float* __restrict__ out) {
    int idx = blockIdx.x * 256 + threadIdx.x;
    if (idx >= BF3 / 2) return;
    int x2 = idx % FX2;
    int t = idx / FX2;
    int y = t % FDIM;
    t /= FDIM;
    int z = t % FDIM;
    int b = t / FDIM;
    int x0 = 2 * x2;

    const float* A = aff + b * 16;  // row-major 4x4
    float gz = (float)z - 79.5f;
    float gy = (float)y - 79.5f;
    float gx = (float)x0 - 79.5f;

    float lz0 = fmaf(A[0], gz, fmaf(A[1], gy, fmaf(A[2], gx, 79.5f + A[3])));
    float ly0 = fmaf(A[4], gz, fmaf(A[5], gy, fmaf(A[6], gx, 79.5f + A[7])));
    float lx0 = fmaf(A[8], gz, fmaf(A[9], gy, fmaf(A[10], gx, 79.5f + A[11])));
    float lz1 = lz0 + A[2];
    float ly1 = ly0 + A[6];
    float lx1 = lx0 + A[10];

    const float4* ub = g_u4 + b * F3;
    const float* xb = xin + b * F3;

    float4 u0 = trisample4<FDIM>(ub, lz0, ly0, lx0);
    float4 u1 = trisample4<FDIM>(ub, lz1, ly1, lx1);
    float s0 = trisample1<FDIM>(xb, lz0 + u0.x, ly0 + u0.y, lx0 + u0.z);
    float s1 = trisample1<FDIM>(xb, lz1 + u1.x, ly1 + u1.y, lx1 + u1.z);

    *reinterpret_cast<float2*>(out + b * F3 + z * F2 + y * FDIM + x0) =
        make_float2(s0, s1);
}

extern "C" void kernel_launch(void* const* d_in, const int* in_sizes, int n_in,
                              void* d_out, int out_size) {
    const float* x = nullptr;
    const float* aff = nullptr;
    const float* svf = nullptr;
    for (int i = 0; i < n_in; i++) {
        if (in_sizes[i] == BATCH * 16) {
            aff = (const float*)d_in[i];
        } else if (in_sizes[i] == BATCH * SV * SV * SV * 3) {
            svf = (const float*)d_in[i];
        } else {
            x = (const float*)d_in[i];
        }
    }

    const int gC  = (BC3 + 255) / 256;
    const int gC2 = (BC3 / 2 + 255) / 256;
    const int gF2 = (BF3 / 2 + 255) / 256;

    k_resize_svf<<<gC, 256>>>(svf);
    // 7 steps: ends (DIR=0 last) with result in g_v4b
    k_square<0><<<gC2, 256>>>();
    k_square<1><<<gC2, 256>>>();
    k_square<0><<<gC2, 256>>>();
    k_square<1><<<gC2, 256>>>();
    k_square<0><<<gC2, 256>>>();
    k_square<1><<<gC2, 256>>>();
    k_square<0><<<gC2, 256>>>();
    k_upsample<<<gC, 256>>>();
    k_final<<<gF2, 256>>>(x, aff, (float*)d_out);
}